// round 16
// baseline (speedup 1.0000x reference)
#include <cuda_runtime.h>
#include <math.h>

#define NMAX   1024
#define TW     8
#define TH     8
#define RT     512            // threads per block
#define PIX    64             // pixels per tile (8x8)
#define NSPL   8              // split-transmittance ways (threads per pixel)
#define ROUNDS (NMAX / RT)    // 2 cull rounds
#define PREB   32             // preprocess blocks (1 math warp each)
#define GPB    (NMAX / PREB)  // 32 gaussians per preprocess block
#define OPCUT  (-5.53f)       // sigmoid(o) > 1/255  <=>  o > -5.5373 (conservative)

static __device__ __forceinline__ float finf() { return __int_as_float(0x7f800000); }

// UNSORTED per-gaussian data (render sorts survivors per tile)
__device__ float4 u_A[NMAX]; // mx, my, conA, conB
__device__ float4 u_B[NMAX]; // conC, op, colR, colG
__device__ float2 u_C[NMAX]; // colB, depth
__device__ float4 u_D[NMAX]; // xmin, xmax, ymin, ymax (empty box => culled)
__device__ float  u_K[NMAX]; // depth key (+inf if culled)
// Cross-block sync
__device__ int g_done = 0;   // # preprocess blocks finished
__device__ int g_exit = 0;   // monotone exit counter (never reset)

__global__ __launch_bounds__(RT, 3) void gs_fused_kernel(
    const float* __restrict__ means3d,   // [N,3]
    const float* __restrict__ quats,     // [N,4]
    const float* __restrict__ scales,    // [N,3]
    const float* __restrict__ opac,      // [N]
    const float* __restrict__ sh,        // [N,4,3]
    const float* __restrict__ c2w,       // [4,4]
    const float* __restrict__ Ks,        // [3,3]
    const int*   __restrict__ wptr,
    float* __restrict__ out,
    int N, int pixels)
{
    __shared__ float4 cA[NMAX];
    __shared__ float4 cB[NMAX];
    __shared__ float2 cC[NMAX];
    __shared__ float  skeys[NMAX];
    __shared__ int    sidx[NMAX];
    __shared__ float4 pA[NSPL - 1][PIX];
    __shared__ float2 pC[NSPL - 1][PIX];
    __shared__ int    warpCnt[ROUNDS * 16];

    const int tid = threadIdx.x;

    if (blockIdx.x < PREB) {
        // ================= PREPROCESS BLOCK (math only, 1 warp) =================
        const int i = blockIdx.x * GPB + tid;
        if (tid < GPB && i < N) {
            const float SH_C0 = 0.28209479177387814f;
            const float SH_C1 = 0.4886025119029199f;
            const float NEARP = 0.01f;
            const float FARP  = 1e10f;
            const float LOWPASS = 0.3f;

            const float4 q4  = *(const float4*)(quats + i * 4);
            const float4 sh0 = *(const float4*)(sh + i * 12);
            const float4 sh1 = *(const float4*)(sh + i * 12 + 4);
            const float4 sh2 = *(const float4*)(sh + i * 12 + 8);
            float m0 = means3d[i * 3 + 0], m1 = means3d[i * 3 + 1], m2 = means3d[i * 3 + 2];
            float s0 = scales[i * 3 + 0], s1 = scales[i * 3 + 1], s2v = scales[i * 3 + 2];
            float opraw = opac[i];

            float Rw[3][3];
            #pragma unroll
            for (int r = 0; r < 3; r++)
                #pragma unroll
                for (int c = 0; c < 3; c++)
                    Rw[r][c] = c2w[c * 4 + r];
            float ct0 = c2w[3], ct1 = c2w[7], ct2 = c2w[11];
            float tw[3];
            #pragma unroll
            for (int r = 0; r < 3; r++)
                tw[r] = -(Rw[r][0] * ct0 + Rw[r][1] * ct1 + Rw[r][2] * ct2);

            float fx = Ks[0], cx = Ks[2], fy = Ks[4], cy = Ks[5];

            float x = Rw[0][0] * m0 + Rw[0][1] * m1 + Rw[0][2] * m2 + tw[0];
            float y = Rw[1][0] * m0 + Rw[1][1] * m1 + Rw[1][2] * m2 + tw[1];
            float z = Rw[2][0] * m0 + Rw[2][1] * m1 + Rw[2][2] * m2 + tw[2];

            bool valid = (z > NEARP) && (z < FARP);
            float zs = valid ? z : 1.0f;
            float izs = 1.0f / zs;
            float m2x = fx * x * izs + cx;
            float m2y = fy * y * izs + cy;

            float qw = q4.x, qx = q4.y, qy = q4.z, qz = q4.w;
            float qn = rsqrtf(qw * qw + qx * qx + qy * qy + qz * qz);
            qw *= qn; qx *= qn; qy *= qn; qz *= qn;
            float Rg[3][3];
            Rg[0][0] = 1.f - 2.f * (qy * qy + qz * qz);
            Rg[0][1] = 2.f * (qx * qy - qw * qz);
            Rg[0][2] = 2.f * (qx * qz + qw * qy);
            Rg[1][0] = 2.f * (qx * qy + qw * qz);
            Rg[1][1] = 1.f - 2.f * (qx * qx + qz * qz);
            Rg[1][2] = 2.f * (qy * qz - qw * qx);
            Rg[2][0] = 2.f * (qx * qz - qw * qy);
            Rg[2][1] = 2.f * (qy * qz + qw * qx);
            Rg[2][2] = 1.f - 2.f * (qx * qx + qy * qy);

            float sq[3] = { s0 * s0, s1 * s1, s2v * s2v };

            float cov3[3][3];
            #pragma unroll
            for (int r = 0; r < 3; r++)
                #pragma unroll
                for (int c = 0; c < 3; c++)
                    cov3[r][c] = Rg[r][0] * Rg[c][0] * sq[0]
                               + Rg[r][1] * Rg[c][1] * sq[1]
                               + Rg[r][2] * Rg[c][2] * sq[2];

            float Vc[3][3];
            #pragma unroll
            for (int r = 0; r < 3; r++)
                #pragma unroll
                for (int c = 0; c < 3; c++)
                    Vc[r][c] = Rw[r][0] * cov3[0][c] + Rw[r][1] * cov3[1][c] + Rw[r][2] * cov3[2][c];
            float cc[3][3];
            #pragma unroll
            for (int r = 0; r < 3; r++)
                #pragma unroll
                for (int c = 0; c < 3; c++)
                    cc[r][c] = Vc[r][0] * Rw[c][0] + Vc[r][1] * Rw[c][1] + Vc[r][2] * Rw[c][2];

            float j00 = fx * izs, j02 = -fx * x * izs * izs;
            float j11 = fy * izs, j12 = -fy * y * izs * izs;
            float a = j00 * (cc[0][0] * j00 + cc[0][2] * j02)
                    + j02 * (cc[2][0] * j00 + cc[2][2] * j02);
            float b = j00 * (cc[0][1] * j11 + cc[0][2] * j12)
                    + j02 * (cc[2][1] * j11 + cc[2][2] * j12);
            float c = j11 * (cc[1][1] * j11 + cc[1][2] * j12)
                    + j12 * (cc[2][1] * j11 + cc[2][2] * j12);
            a += LOWPASS;
            c += LOWPASS;
            float det = a * c - b * b;
            valid = valid && (det > 0.f);
            float dets = (det > 0.f) ? det : 1.0f;
            float idet = 1.0f / dets;
            float conA = c * idet, conB = -b * idet, conC = a * idet;

            float dx3 = m0 - ct0, dy3 = m1 - ct1, dz3 = m2 - ct2;
            float dn = sqrtf(dx3 * dx3 + dy3 * dy3 + dz3 * dz3);
            dn = fmaxf(dn, 1e-8f);
            float idn = 1.0f / dn;
            float dxn = dx3 * idn, dyn = dy3 * idn, dzn = dz3 * idn;
            float shv[12] = { sh0.x, sh0.y, sh0.z, sh0.w, sh1.x, sh1.y, sh1.z, sh1.w,
                              sh2.x, sh2.y, sh2.z, sh2.w };
            float col[3];
            #pragma unroll
            for (int ch = 0; ch < 3; ch++) {
                float v = SH_C0 * shv[ch]
                        - SH_C1 * dyn * shv[3 + ch]
                        + SH_C1 * dzn * shv[6 + ch]
                        - SH_C1 * dxn * shv[9 + ch];
                col[ch] = fmaxf(v + 0.5f, 0.0f);
            }

            float op = 1.0f / (1.0f + __expf(-opraw));
            op = valid ? op : 0.0f;

            float xmin = 1e30f, xmax = -1e30f, ymin = 1e30f, ymax = -1e30f;
            bool lit = valid && (opraw > OPCUT);
            if (lit) {
                float sg = fminf(5.55f, logf(255.f * op));
                float rx = sqrtf(2.f * sg * a);
                float ry = sqrtf(2.f * sg * c);
                xmin = m2x - rx; xmax = m2x + rx;
                ymin = m2y - ry; ymax = m2y + ry;
            } else {
                op = 0.f;
            }

            u_A[i] = make_float4(m2x, m2y, conA, conB);
            u_B[i] = make_float4(conC, op, col[0], col[1]);
            u_C[i] = make_float2(col[2], z);
            u_D[i] = make_float4(xmin, xmax, ymin, ymax);
            u_K[i] = lit ? z : finf();
        }
        __threadfence();
        __syncthreads();
        if (tid == 0) atomicAdd(&g_done, 1);
    } else {
        // ================= RENDER BLOCK =================
        if (tid == 0) {
            while (*(volatile int*)&g_done < PREB) __nanosleep(64);
        }
        __syncthreads();
        __threadfence();

        const int warp = tid >> 5;
        const int lane = tid & 31;
        const unsigned lanemask = (1u << lane) - 1u;
        const int pid  = tid & (PIX - 1);    // pixel within 8x8 tile
        const int qtr  = tid >> 6;           // 0..7: eighth of the survivor list

        const int W = *wptr;
        const int H = pixels / W;
        const int tilesX = (W + TW - 1) / TW;
        const int tilesY = (H + TH - 1) / TH;
        const int tileCount = tilesX * tilesY;
        const int rstride = gridDim.x - PREB;

        for (int t = blockIdx.x - PREB; t < tileCount; t += rstride) {
            int tx = t % tilesX;
            int ty = t / tilesX;
            int x0 = tx * TW;
            int y0 = ty * TH;

            int pxI = x0 + (pid & (TW - 1));
            int pyI = y0 + (pid / TW);
            bool inb = (pxI < W) && (pyI < H);
            float px = (float)pxI + 0.5f;
            float py = (float)pyI + 0.5f;

            float xlo = (float)x0, xhi = (float)(x0 + TW);
            float ylo = (float)y0, yhi = (float)(y0 + TH);

            // ---- cull: 2 ballot rounds, record (key, gidx) of survivors ----
            unsigned ball[ROUNDS];
            unsigned predMask = 0;
            #pragma unroll
            for (int r = 0; r < ROUNDS; r++) {
                int gi = r * RT + tid;
                bool pred = false;
                if (gi < N) {
                    float4 D = u_D[gi];
                    pred = (D.y >= xlo) && (D.x <= xhi) && (D.w >= ylo) && (D.z <= yhi);
                }
                ball[r] = __ballot_sync(0xffffffffu, pred);
                predMask |= pred ? (1u << r) : 0u;
                if (lane == 0) warpCnt[r * 16 + warp] = __popc(ball[r]);
            }
            __syncthreads();

            int wb[ROUNDS];
            int rb = 0;
            #pragma unroll
            for (int r = 0; r < ROUNDS; r++) {
                int wbase = rb;
                #pragma unroll
                for (int w2 = 0; w2 < 16; w2++) {
                    int cw = warpCnt[r * 16 + w2];
                    if (w2 < warp) wbase += cw;
                    rb += cw;
                }
                wb[r] = wbase;
            }
            const int total = rb;

            #pragma unroll
            for (int r = 0; r < ROUNDS; r++) {
                if (predMask & (1u << r)) {
                    int gi = r * RT + tid;
                    int off = wb[r] + __popc(ball[r] & lanemask);
                    skeys[off] = u_K[gi];
                    sidx[off]  = gi;
                }
            }
            __syncthreads();

            // ---- stable rank-sort survivors by (key, gidx); gather sorted ----
            for (int s = tid; s < total; s += RT) {
                float ki = skeys[s];
                int   gi = sidx[s];
                int rank = 0;
                #pragma unroll 4
                for (int j = 0; j < total; j++) {
                    float kj = skeys[j];
                    rank += (kj < ki) || ((kj == ki) && (sidx[j] < gi));
                }
                cA[rank] = u_A[gi];
                cB[rank] = u_B[gi];
                cC[rank] = u_C[gi];
            }
            __syncthreads();

            // ---- composite: 8-way split-T, branchless, 2x unrolled ----
            const int s = (total + NSPL - 1) / NSPL;
            int jbeg = qtr * s;  if (jbeg > total) jbeg = total;
            int jend = jbeg + s; if (jend > total) jend = total;

            float T = 1.0f;
            float r_ = 0.f, g = 0.f, b = 0.f, accW = 0.f, accD = 0.f;

            int j = jbeg;
            for (; j + 1 < jend; j += 2) {
                if (__all_sync(0xffffffffu, T < 1e-5f)) break;
                float4 A0 = cA[j],     A1 = cA[j + 1];
                float4 B0 = cB[j],     B1 = cB[j + 1];
                float dx0 = px - A0.x, dy0 = py - A0.y;
                float dx1 = px - A1.x, dy1 = py - A1.y;
                float s0 = 0.5f * (A0.z * dx0 * dx0 + B0.x * dy0 * dy0) + A0.w * dx0 * dy0;
                float s1 = 0.5f * (A1.z * dx1 * dx1 + B1.x * dy1 * dy1) + A1.w * dx1 * dy1;
                float a0 = fminf(B0.y * __expf(-s0), 0.999f);
                float a1 = fminf(B1.y * __expf(-s1), 0.999f);
                a0 = (s0 >= 0.f && s0 <= 5.55f && a0 >= (1.f / 255.f)) ? a0 : 0.f;
                a1 = (s1 >= 0.f && s1 <= 5.55f && a1 >= (1.f / 255.f)) ? a1 : 0.f;
                float2 C0 = cC[j], C1 = cC[j + 1];
                float w0 = a0 * T;
                r_ += w0 * B0.z; g += w0 * B0.w; b += w0 * C0.x;
                accD += w0 * C0.y; accW += w0;
                T *= (1.0f - a0);
                float w1 = a1 * T;
                r_ += w1 * B1.z; g += w1 * B1.w; b += w1 * C1.x;
                accD += w1 * C1.y; accW += w1;
                T *= (1.0f - a1);
            }
            if (j < jend && !(T < 1e-5f)) {
                float4 A0 = cA[j];
                float4 B0 = cB[j];
                float dx0 = px - A0.x, dy0 = py - A0.y;
                float s0 = 0.5f * (A0.z * dx0 * dx0 + B0.x * dy0 * dy0) + A0.w * dx0 * dy0;
                float a0 = fminf(B0.y * __expf(-s0), 0.999f);
                a0 = (s0 >= 0.f && s0 <= 5.55f && a0 >= (1.f / 255.f)) ? a0 : 0.f;
                float2 C0 = cC[j];
                float w0 = a0 * T;
                r_ += w0 * B0.z; g += w0 * B0.w; b += w0 * C0.x;
                accD += w0 * C0.y; accW += w0;
                T *= (1.0f - a0);
            }

            // ---- combine: res = p0 + T0*p1 + T0*T1*p2 + ... (telescoping) ----
            if (qtr > 0) {
                pA[qtr - 1][pid] = make_float4(r_, g, b, accW);
                pC[qtr - 1][pid] = make_float2(accD, T);
            }
            __syncthreads();
            if (qtr == 0 && inb) {
                float tAcc = T;
                #pragma unroll
                for (int k = 0; k < NSPL - 1; k++) {
                    float4 P = pA[k][pid];
                    float2 Q = pC[k][pid];
                    r_   += tAcc * P.x;
                    g    += tAcc * P.y;
                    b    += tAcc * P.z;
                    accW += tAcc * P.w;
                    accD += tAcc * Q.x;
                    tAcc *= Q.y;
                }
                int p = pyI * W + pxI;
                float ed = accD / fmaxf(accW, 1e-10f);
                ((float4*)out)[p] = make_float4(r_, g, b, ed);
                out[pixels * 4 + p] = accW;
            }
            __syncthreads();   // protect smem reuse across grid-stride tiles
        }
    }

    // ================= EXIT / RESET =================
    __syncthreads();
    if (tid == 0) {
        int old = atomicAdd(&g_exit, 1);
        if (old % (int)gridDim.x == (int)gridDim.x - 1) {
            *(volatile int*)&g_done = 0;   // last block out resets for next replay
        }
    }
}

extern "C" void kernel_launch(void* const* d_in, const int* in_sizes, int n_in,
                              void* d_out, int out_size) {
    const float* means3d = (const float*)d_in[0];
    const float* quats   = (const float*)d_in[1];
    const float* scales  = (const float*)d_in[2];
    const float* opac    = (const float*)d_in[3];
    const float* sh      = (const float*)d_in[4];
    const float* c2w     = (const float*)d_in[5];
    const float* Ks      = (const float*)d_in[6];
    const int*   wptr    = (const int*)d_in[7];
    float* out = (float*)d_out;

    int N = in_sizes[0] / 3;
    if (N > NMAX) N = NMAX;
    int pixels = out_size / 5;

    int renderBlocks = (pixels + PIX - 1) / PIX;
    if (renderBlocks < 1) renderBlocks = 1;
    gs_fused_kernel<<<PREB + renderBlocks, RT>>>(means3d, quats, scales, opac, sh,
                                                 c2w, Ks, wptr, out, N, pixels);
}